// round 1
// baseline (speedup 1.0000x reference)
#include <cuda_runtime.h>
#include <math.h>

#define GNODES 50000
#define DSTALK 3
#define HCH 64
#define IN_DIM 256
#define OUT_DIM 40
#define NLAYERS 4
#define NNZ_E 2400000
#define NEXT (GNODES * DSTALK)   // 150000

// ---------------- scratch (static device globals; no allocs) ----------------
__device__ float g_HH[NEXT * HCH];   // h (== h0 between layers), also [G,192] view
__device__ float g_T[NEXT * HCH];    // post left+right transform
__device__ float g_ACC[NEXT * HCH];  // SpMM accumulator

// ---------------- lin1: C = elu(x @ W1^T + b1), written into g_HH -----------
// M=50000, N=192, K=256. BM=BN=64, BK=16, 256 threads, 4x4 microtile.
__global__ __launch_bounds__(256) void lin1_kernel(const float* __restrict__ x,
                                                   const float* __restrict__ w,
                                                   const float* __restrict__ b) {
    __shared__ float As[16][68];
    __shared__ float Bs[16][68];
    const int bm = blockIdx.x * 64;
    const int bn = blockIdx.y * 64;
    const int tid = threadIdx.x;
    const int tx = tid & 15;        // 0..15 (cols)
    const int ty = tid >> 4;        // 0..15 (rows)

    float acc[4][4];
#pragma unroll
    for (int i = 0; i < 4; i++)
#pragma unroll
        for (int j = 0; j < 4; j++) acc[i][j] = 0.f;

    const int lr = tid >> 2;            // 0..63 row within tile
    const int lk = (tid & 3) * 4;       // 0,4,8,12

    for (int k0 = 0; k0 < IN_DIM; k0 += 16) {
        float4 av = make_float4(0.f, 0.f, 0.f, 0.f);
        int gr = bm + lr;
        if (gr < GNODES) av = *(const float4*)&x[gr * IN_DIM + k0 + lk];
        As[lk + 0][lr] = av.x; As[lk + 1][lr] = av.y;
        As[lk + 2][lr] = av.z; As[lk + 3][lr] = av.w;

        int nr = bn + lr;  // always < 192
        float4 bv = *(const float4*)&w[nr * IN_DIM + k0 + lk];
        Bs[lk + 0][lr] = bv.x; Bs[lk + 1][lr] = bv.y;
        Bs[lk + 2][lr] = bv.z; Bs[lk + 3][lr] = bv.w;
        __syncthreads();

#pragma unroll
        for (int k = 0; k < 16; k++) {
            float ar[4], br[4];
#pragma unroll
            for (int i = 0; i < 4; i++) ar[i] = As[k][ty * 4 + i];
#pragma unroll
            for (int j = 0; j < 4; j++) br[j] = Bs[k][tx * 4 + j];
#pragma unroll
            for (int i = 0; i < 4; i++)
#pragma unroll
                for (int j = 0; j < 4; j++) acc[i][j] += ar[i] * br[j];
        }
        __syncthreads();
    }

#pragma unroll
    for (int i = 0; i < 4; i++) {
        int gr = bm + ty * 4 + i;
        if (gr >= GNODES) continue;
#pragma unroll
        for (int j = 0; j < 4; j++) {
            int n = bn + tx * 4 + j;
            float v = acc[i][j] + b[n];
            v = (v > 0.f) ? v : (expf(v) - 1.f);
            g_HH[gr * 192 + n] = v;   // [G,192] == [N,64] layout
        }
    }
}

// ------- fused left(3x3 stalk) + right(64x64 channel) transform -------------
// Per block: 16 graph nodes -> 48 extended rows. T = leftmix(HH) @ R^T
__global__ __launch_bounds__(256) void transform_kernel(const float* __restrict__ leftw,
                                                        const float* __restrict__ rightw) {
    __shared__ float sh_h[48 * 65];
    __shared__ float sh_t[48 * 65];
    __shared__ float sh_R[64 * 65];
    const int tid = threadIdx.x;
    const int rowbase = blockIdx.x * 48;   // 3125 blocks * 48 = 150000 exact

    for (int i = tid; i < 64 * 64; i += 256)
        sh_R[(i >> 6) * 65 + (i & 63)] = rightw[i];
    for (int i = tid; i < 48 * 64; i += 256)
        sh_h[(i >> 6) * 65 + (i & 63)] = g_HH[(rowbase + (i >> 6)) * 64 + (i & 63)];

    float Lw[9];
#pragma unroll
    for (int i = 0; i < 9; i++) Lw[i] = leftw[i];
    __syncthreads();

    for (int i = tid; i < 48 * 64; i += 256) {
        int row = i >> 6, c = i & 63;
        int e = row % 3;
        int gl = row - e;  // g_local*3
        float t = Lw[e * 3 + 0] * sh_h[(gl + 0) * 65 + c]
                + Lw[e * 3 + 1] * sh_h[(gl + 1) * 65 + c]
                + Lw[e * 3 + 2] * sh_h[(gl + 2) * 65 + c];
        sh_t[row * 65 + c] = t;
    }
    __syncthreads();

    // out[row, cp] = sum_c t[row][c] * R[cp][c]
    const int cp = tid & 63;     // output channel
    const int rg = tid >> 6;     // 0..3 row group
    float acc[12];
#pragma unroll
    for (int i = 0; i < 12; i++) acc[i] = 0.f;
#pragma unroll 16
    for (int c = 0; c < 64; c++) {
        float rv = sh_R[cp * 65 + c];           // conflict-free (pad 65)
#pragma unroll
        for (int i = 0; i < 12; i++)
            acc[i] += sh_t[(rg + 4 * i) * 65 + c] * rv;  // warp broadcast
    }
#pragma unroll
    for (int i = 0; i < 12; i++)
        g_T[(rowbase + rg + 4 * i) * 64 + cp] = acc[i];
}

// ---------------- zero ACC ---------------------------------------------------
__global__ __launch_bounds__(256) void zero_acc_kernel() {
    int idx = blockIdx.x * blockDim.x + threadIdx.x;
    if (idx < NEXT * 16)
        ((float4*)g_ACC)[idx] = make_float4(0.f, 0.f, 0.f, 0.f);
}

// ---------------- SpMM: ACC[r,:] += v * T[c,:]  (COO, atomic) ----------------
__global__ __launch_bounds__(256) void spmm_kernel(const int* __restrict__ rows,
                                                   const int* __restrict__ cols,
                                                   const float* __restrict__ vals) {
    const int lane = threadIdx.x & 31;
    const int gwarp = (blockIdx.x * blockDim.x + threadIdx.x) >> 5;
    const int nwarp = (gridDim.x * blockDim.x) >> 5;
    const float* __restrict__ T = g_T;

    for (int base = gwarp * 32; base < NNZ_E; base += nwarp * 32) {
        int e = base + lane;              // NNZ % 32 == 0, always valid
        int r = rows[e];
        int c = cols[e];
        float v = vals[e];
#pragma unroll 1
        for (int i = 0; i < 32; i++) {
            int ri = __shfl_sync(0xffffffffu, r, i);
            int ci = __shfl_sync(0xffffffffu, c, i);
            float vi = __shfl_sync(0xffffffffu, v, i);
            float a0 = __ldg(&T[ci * 64 + lane]);
            float a1 = __ldg(&T[ci * 64 + 32 + lane]);
            atomicAdd(&g_ACC[ri * 64 + lane], vi * a0);
            atomicAdd(&g_ACC[ri * 64 + 32 + lane], vi * a1);
        }
    }
}

// ---------------- epilogue: h0 = gate*h0 - elu(acc); zero ACC ----------------
__global__ __launch_bounds__(256) void epilogue_kernel(const float* __restrict__ eps, int l) {
    int idx = blockIdx.x * blockDim.x + threadIdx.x;  // over NEXT*16 float4
    if (idx >= NEXT * 16) return;
    int n = idx >> 4;
    int d = n % 3;
    float gate = 1.f + tanhf(eps[l * 3 + d]);
    float4 a = ((const float4*)g_ACC)[idx];
    float4 h0 = ((const float4*)g_HH)[idx];
    float ex, ey, ez, ew;
    ex = (a.x > 0.f) ? a.x : (expf(a.x) - 1.f);
    ey = (a.y > 0.f) ? a.y : (expf(a.y) - 1.f);
    ez = (a.z > 0.f) ? a.z : (expf(a.z) - 1.f);
    ew = (a.w > 0.f) ? a.w : (expf(a.w) - 1.f);
    float4 r;
    r.x = gate * h0.x - ex;
    r.y = gate * h0.y - ey;
    r.z = gate * h0.z - ez;
    r.w = gate * h0.w - ew;
    ((float4*)g_HH)[idx] = r;
    ((float4*)g_ACC)[idx] = make_float4(0.f, 0.f, 0.f, 0.f);  // ready for next layer
}

// ---------------- lin2 + log_softmax ----------------------------------------
// 16 g-rows per block; 8 warps, each warp 2 rows; lane covers out o=lane and o=lane+32 (lane<8)
__global__ __launch_bounds__(256) void out_kernel(const float* __restrict__ w2,
                                                  const float* __restrict__ b2,
                                                  float* __restrict__ out) {
    __shared__ float sW[40 * 193];
    __shared__ float sH[16 * 192];
    const int tid = threadIdx.x;
    const int gbase = blockIdx.x * 16;   // 3125 blocks * 16 = 50000 exact

    for (int i = tid; i < 40 * 192; i += 256)
        sW[(i / 192) * 193 + (i % 192)] = w2[i];
    for (int i = tid; i < 16 * 192; i += 256)
        sH[i] = g_HH[gbase * 192 + i];
    __syncthreads();

    const int warp = tid >> 5, lane = tid & 31;
#pragma unroll
    for (int rr = 0; rr < 2; rr++) {
        int row = warp * 2 + rr;
        int g = gbase + row;
        float acc1 = 0.f, acc2 = 0.f;
        const float* hrow = &sH[row * 192];
#pragma unroll 8
        for (int j = 0; j < 192; j++) {
            float hv = hrow[j];                       // warp broadcast
            acc1 += hv * sW[lane * 193 + j];
            if (lane < 8) acc2 += hv * sW[(lane + 32) * 193 + j];
        }
        acc1 += b2[lane];
        float v2 = (lane < 8) ? (acc2 + b2[lane + 32]) : -INFINITY;

        float m = fmaxf(acc1, v2);
#pragma unroll
        for (int off = 16; off; off >>= 1) m = fmaxf(m, __shfl_xor_sync(0xffffffffu, m, off));
        float s = expf(acc1 - m) + ((lane < 8) ? expf(v2 - m) : 0.f);
#pragma unroll
        for (int off = 16; off; off >>= 1) s += __shfl_xor_sync(0xffffffffu, s, off);
        float ls = m + logf(s);

        out[g * OUT_DIM + lane] = acc1 - ls;
        if (lane < 8) out[g * OUT_DIM + 32 + lane] = v2 - ls;
    }
}

// ---------------- launch -----------------------------------------------------
extern "C" void kernel_launch(void* const* d_in, const int* in_sizes, int n_in,
                              void* d_out, int out_size) {
    const float* x   = (const float*)d_in[0];
    const int*   lr  = (const int*)d_in[1];
    const int*   lc  = (const int*)d_in[2];
    const float* lv  = (const float*)d_in[3];
    const float* w1  = (const float*)d_in[4];
    const float* b1  = (const float*)d_in[5];
    const float* lw  = (const float*)d_in[6];   // [L,3,3]
    const float* rw  = (const float*)d_in[7];   // [L,64,64]
    const float* eps = (const float*)d_in[8];   // [L,3,1]
    const float* w2  = (const float*)d_in[9];
    const float* b2  = (const float*)d_in[10];
    float* out = (float*)d_out;

    lin1_kernel<<<dim3(782, 3), 256>>>(x, w1, b1);
    zero_acc_kernel<<<(NEXT * 16 + 255) / 256, 256>>>();
    for (int l = 0; l < NLAYERS; l++) {
        transform_kernel<<<NEXT / 48, 256>>>(lw + l * 9, rw + l * 64 * 64);
        spmm_kernel<<<1480, 256>>>(lr, lc, lv);
        epilogue_kernel<<<(NEXT * 16 + 255) / 256, 256>>>(eps, l);
    }
    out_kernel<<<GNODES / 16, 256>>>(w2, b2, out);
}

// round 3
// speedup vs baseline: 1.2426x; 1.2426x over previous
#include <cuda_runtime.h>
#include <math.h>

#define GNODES 50000
#define DSTALK 3
#define HCH 64
#define IN_DIM 256
#define OUT_DIM 40
#define NLAYERS 4
#define NNZ_E 2400000
#define NEXT (GNODES * DSTALK)   // 150000

// ---------------- scratch (static device globals; no allocs) ----------------
__device__ float g_HH[NEXT * HCH];   // h (== h0 between layers), also [G,192] view
__device__ float g_T[NEXT * HCH];    // post left+right transform
__device__ float g_ACC[NEXT * HCH];  // SpMM accumulator

// ---------------- vector red ------------------------------------------------
__device__ __forceinline__ void red_add_v4(float4* addr, float4 p) {
    asm volatile("red.global.add.v4.f32 [%0], {%1, %2, %3, %4};"
                 :: "l"(addr), "f"(p.x), "f"(p.y), "f"(p.z), "f"(p.w)
                 : "memory");
}

// ---------------- lin1: g_HH = elu(x @ W1^T + b1) ---------------------------
// M=50000, N=192, K=256. BM=128, BN=64, BK=16, 256 threads, 8x4 microtile.
__global__ __launch_bounds__(256) void lin1_kernel(const float* __restrict__ x,
                                                   const float* __restrict__ w,
                                                   const float* __restrict__ b) {
    __shared__ float As[16][132];   // [k][m], row stride 132*4=528B (16B aligned)
    __shared__ float Bs[16][68];    // [k][n]
    const int bm = blockIdx.x * 128;
    const int bn = blockIdx.y * 64;
    const int tid = threadIdx.x;
    const int tx = tid & 15;        // 0..15 -> n microtile (4 cols)
    const int ty = tid >> 4;        // 0..15 -> m microtile (8 rows)

    float acc[8][4];
#pragma unroll
    for (int i = 0; i < 8; i++)
#pragma unroll
        for (int j = 0; j < 4; j++) acc[i][j] = 0.f;

    const int lrA = tid >> 1;           // 0..127
    const int lkA = (tid & 1) * 8;      // 0 or 8
    const int lrB = tid >> 2;           // 0..63
    const int lkB = (tid & 3) * 4;      // 0,4,8,12

    for (int k0 = 0; k0 < IN_DIM; k0 += 16) {
        float4 a0 = make_float4(0.f, 0.f, 0.f, 0.f);
        float4 a1 = make_float4(0.f, 0.f, 0.f, 0.f);
        int gr = bm + lrA;
        if (gr < GNODES) {
            a0 = *(const float4*)&x[gr * IN_DIM + k0 + lkA];
            a1 = *(const float4*)&x[gr * IN_DIM + k0 + lkA + 4];
        }
        As[lkA + 0][lrA] = a0.x; As[lkA + 1][lrA] = a0.y;
        As[lkA + 2][lrA] = a0.z; As[lkA + 3][lrA] = a0.w;
        As[lkA + 4][lrA] = a1.x; As[lkA + 5][lrA] = a1.y;
        As[lkA + 6][lrA] = a1.z; As[lkA + 7][lrA] = a1.w;

        float4 bv = *(const float4*)&w[(bn + lrB) * IN_DIM + k0 + lkB];
        Bs[lkB + 0][lrB] = bv.x; Bs[lkB + 1][lrB] = bv.y;
        Bs[lkB + 2][lrB] = bv.z; Bs[lkB + 3][lrB] = bv.w;
        __syncthreads();

#pragma unroll
        for (int k = 0; k < 16; k++) {
            float4 ar0 = *(float4*)&As[k][ty * 8];
            float4 ar1 = *(float4*)&As[k][ty * 8 + 4];
            float4 br  = *(float4*)&Bs[k][tx * 4];
            float ar[8] = {ar0.x, ar0.y, ar0.z, ar0.w, ar1.x, ar1.y, ar1.z, ar1.w};
            float brr[4] = {br.x, br.y, br.z, br.w};
#pragma unroll
            for (int i = 0; i < 8; i++)
#pragma unroll
                for (int j = 0; j < 4; j++) acc[i][j] += ar[i] * brr[j];
        }
        __syncthreads();
    }

    float4 bias = *(const float4*)&b[bn + tx * 4];
    float bb[4] = {bias.x, bias.y, bias.z, bias.w};
#pragma unroll
    for (int i = 0; i < 8; i++) {
        int gr = bm + ty * 8 + i;
        if (gr >= GNODES) continue;
        float4 r;
        float v;
        v = acc[i][0] + bb[0]; r.x = (v > 0.f) ? v : (expf(v) - 1.f);
        v = acc[i][1] + bb[1]; r.y = (v > 0.f) ? v : (expf(v) - 1.f);
        v = acc[i][2] + bb[2]; r.z = (v > 0.f) ? v : (expf(v) - 1.f);
        v = acc[i][3] + bb[3]; r.w = (v > 0.f) ? v : (expf(v) - 1.f);
        *(float4*)&g_HH[gr * 192 + bn + tx * 4] = r;
    }
}

// ------- fused left(3x3 stalk) + right(64x64 channel) transform -------------
// Per block: 16 graph nodes -> 48 extended rows. T = leftmix(HH) @ R^T
__global__ __launch_bounds__(256) void transform_kernel(const float* __restrict__ leftw,
                                                        const float* __restrict__ rightw) {
    __shared__ float sh_h[48 * 68];
    __shared__ float sh_t[48 * 68];
    __shared__ float sh_R[64 * 68];
    const int tid = threadIdx.x;
    const int rowbase = blockIdx.x * 48;   // 3125 blocks * 48 = 150000 exact

    // load R: 64x64 -> 1024 float4
    for (int i = tid; i < 1024; i += 256) {
        int row = i >> 4, c4 = i & 15;
        float4 v = ((const float4*)rightw)[i];
        *(float4*)&sh_R[row * 68 + c4 * 4] = v;
    }
    // load h tile: 48x64 -> 768 float4
    for (int i = tid; i < 768; i += 256) {
        int row = i >> 4, c4 = i & 15;
        float4 v = ((const float4*)g_HH)[(rowbase + row) * 16 + c4];
        *(float4*)&sh_h[row * 68 + c4 * 4] = v;
    }

    float Lw[9];
#pragma unroll
    for (int i = 0; i < 9; i++) Lw[i] = leftw[i];
    __syncthreads();

    // left mix (3x3 along stalk dim)
    for (int i = tid; i < 768; i += 256) {
        int row = i >> 4, c4 = i & 15;
        int e = row % 3;
        int gl = row - e;
        float4 h0 = *(float4*)&sh_h[(gl + 0) * 68 + c4 * 4];
        float4 h1 = *(float4*)&sh_h[(gl + 1) * 68 + c4 * 4];
        float4 h2 = *(float4*)&sh_h[(gl + 2) * 68 + c4 * 4];
        float w0 = Lw[e * 3 + 0], w1 = Lw[e * 3 + 1], w2 = Lw[e * 3 + 2];
        float4 t;
        t.x = w0 * h0.x + w1 * h1.x + w2 * h2.x;
        t.y = w0 * h0.y + w1 * h1.y + w2 * h2.y;
        t.z = w0 * h0.z + w1 * h1.z + w2 * h2.z;
        t.w = w0 * h0.w + w1 * h1.w + w2 * h2.w;
        *(float4*)&sh_t[row * 68 + c4 * 4] = t;
    }
    __syncthreads();

    // out[row, cp] = sum_c t[row][c] * R[cp][c]
    const int cp = tid & 63;     // output channel
    const int rg = tid >> 6;     // 0..3 row group
    float acc[12];
#pragma unroll
    for (int i = 0; i < 12; i++) acc[i] = 0.f;
#pragma unroll
    for (int c0 = 0; c0 < 64; c0 += 4) {
        float4 rv = *(float4*)&sh_R[cp * 68 + c0];
#pragma unroll
        for (int i = 0; i < 12; i++) {
            float4 tv = *(float4*)&sh_t[(rg + 4 * i) * 68 + c0];  // warp broadcast
            acc[i] += tv.x * rv.x + tv.y * rv.y + tv.z * rv.z + tv.w * rv.w;
        }
    }
#pragma unroll
    for (int i = 0; i < 12; i++)
        g_T[(rowbase + rg + 4 * i) * 64 + cp] = acc[i];
}

// ---------------- zero ACC ---------------------------------------------------
__global__ __launch_bounds__(256) void zero_acc_kernel() {
    int idx = blockIdx.x * blockDim.x + threadIdx.x;
    if (idx < NEXT * 16)
        ((float4*)g_ACC)[idx] = make_float4(0.f, 0.f, 0.f, 0.f);
}

// ---------------- SpMM: ACC[r,:] += v * T[c,:]  (COO, vector red) -----------
// Half-warp per edge: 16 lanes x float4 = 64 channels.
__global__ __launch_bounds__(256) void spmm_kernel(const int* __restrict__ rows,
                                                   const int* __restrict__ cols,
                                                   const float* __restrict__ vals) {
    const int lane = threadIdx.x & 31;
    const int half = lane >> 4;      // 0/1
    const int hl = lane & 15;        // lane within half-warp
    const int gwarp = (blockIdx.x * blockDim.x + threadIdx.x) >> 5;
    const int nwarp = (gridDim.x * blockDim.x) >> 5;
    const float4* __restrict__ T4 = (const float4*)g_T;
    float4* ACC4 = (float4*)g_ACC;

    for (int base = gwarp * 32; base < NNZ_E; base += nwarp * 32) {
        int e = base + lane;              // NNZ % 32 == 0, always valid
        int r = rows[e];
        int c = cols[e];
        float v = vals[e];
#pragma unroll 1
        for (int i = 0; i < 16; i++) {
            int src = 2 * i + half;
            int ri = __shfl_sync(0xffffffffu, r, src);
            int ci = __shfl_sync(0xffffffffu, c, src);
            float vi = __shfl_sync(0xffffffffu, v, src);
            float4 t = __ldg(&T4[ci * 16 + hl]);
            float4 p;
            p.x = vi * t.x; p.y = vi * t.y; p.z = vi * t.z; p.w = vi * t.w;
            red_add_v4(&ACC4[ri * 16 + hl], p);
        }
    }
}

// ---------------- epilogue: h0 = gate*h0 - elu(acc); zero ACC ----------------
__global__ __launch_bounds__(256) void epilogue_kernel(const float* __restrict__ eps, int l) {
    int idx = blockIdx.x * blockDim.x + threadIdx.x;  // over NEXT*16 float4
    if (idx >= NEXT * 16) return;
    int n = idx >> 4;
    int d = n % 3;
    float gate = 1.f + tanhf(eps[l * 3 + d]);
    float4 a = ((const float4*)g_ACC)[idx];
    float4 h0 = ((const float4*)g_HH)[idx];
    float ex, ey, ez, ew;
    ex = (a.x > 0.f) ? a.x : (expf(a.x) - 1.f);
    ey = (a.y > 0.f) ? a.y : (expf(a.y) - 1.f);
    ez = (a.z > 0.f) ? a.z : (expf(a.z) - 1.f);
    ew = (a.w > 0.f) ? a.w : (expf(a.w) - 1.f);
    float4 r;
    r.x = gate * h0.x - ex;
    r.y = gate * h0.y - ey;
    r.z = gate * h0.z - ez;
    r.w = gate * h0.w - ew;
    ((float4*)g_HH)[idx] = r;
    ((float4*)g_ACC)[idx] = make_float4(0.f, 0.f, 0.f, 0.f);  // ready for next layer
}

// ---------------- lin2 + log_softmax ----------------------------------------
__global__ __launch_bounds__(256) void out_kernel(const float* __restrict__ w2,
                                                  const float* __restrict__ b2,
                                                  float* __restrict__ out) {
    __shared__ float sW[40 * 193];
    __shared__ float sH[16 * 192];
    const int tid = threadIdx.x;
    const int gbase = blockIdx.x * 16;   // 3125 blocks * 16 = 50000 exact

    for (int i = tid; i < 40 * 192; i += 256)
        sW[(i / 192) * 193 + (i % 192)] = w2[i];
    for (int i = tid; i < 16 * 192; i += 256)
        sH[i] = g_HH[gbase * 192 + i];
    __syncthreads();

    const int warp = tid >> 5, lane = tid & 31;
#pragma unroll
    for (int rr = 0; rr < 2; rr++) {
        int row = warp * 2 + rr;
        int g = gbase + row;
        float acc1 = 0.f, acc2 = 0.f;
        const float* hrow = &sH[row * 192];
#pragma unroll 8
        for (int j = 0; j < 192; j++) {
            float hv = hrow[j];                       // warp broadcast
            acc1 += hv * sW[lane * 193 + j];
            if (lane < 8) acc2 += hv * sW[(lane + 32) * 193 + j];
        }
        acc1 += b2[lane];
        float v2 = (lane < 8) ? (acc2 + b2[lane + 32]) : -INFINITY;

        float m = fmaxf(acc1, v2);
#pragma unroll
        for (int off = 16; off; off >>= 1) m = fmaxf(m, __shfl_xor_sync(0xffffffffu, m, off));
        float s = expf(acc1 - m) + ((lane < 8) ? expf(v2 - m) : 0.f);
#pragma unroll
        for (int off = 16; off; off >>= 1) s += __shfl_xor_sync(0xffffffffu, s, off);
        float ls = m + logf(s);

        out[g * OUT_DIM + lane] = acc1 - ls;
        if (lane < 8) out[g * OUT_DIM + 32 + lane] = v2 - ls;
    }
}

// ---------------- launch -----------------------------------------------------
extern "C" void kernel_launch(void* const* d_in, const int* in_sizes, int n_in,
                              void* d_out, int out_size) {
    const float* x   = (const float*)d_in[0];
    const int*   lr  = (const int*)d_in[1];
    const int*   lc  = (const int*)d_in[2];
    const float* lv  = (const float*)d_in[3];
    const float* w1  = (const float*)d_in[4];
    const float* b1  = (const float*)d_in[5];
    const float* lw  = (const float*)d_in[6];   // [L,3,3]
    const float* rw  = (const float*)d_in[7];   // [L,64,64]
    const float* eps = (const float*)d_in[8];   // [L,3,1]
    const float* w2  = (const float*)d_in[9];
    const float* b2  = (const float*)d_in[10];
    float* out = (float*)d_out;

    lin1_kernel<<<dim3((GNODES + 127) / 128, 3), 256>>>(x, w1, b1);
    zero_acc_kernel<<<(NEXT * 16 + 255) / 256, 256>>>();
    for (int l = 0; l < NLAYERS; l++) {
        transform_kernel<<<NEXT / 48, 256>>>(lw + l * 9, rw + l * 64 * 64);
        spmm_kernel<<<1480, 256>>>(lr, lc, lv);
        epilogue_kernel<<<(NEXT * 16 + 255) / 256, 256>>>(eps, l);
    }
    out_kernel<<<GNODES / 16, 256>>>(w2, b2, out);
}

// round 4
// speedup vs baseline: 1.7965x; 1.4457x over previous
#include <cuda_runtime.h>
#include <math.h>

#define GNODES 50000
#define DSTALK 3
#define HCH 64
#define IN_DIM 256
#define OUT_DIM 40
#define NLAYERS 4
#define NNZ_E 2400000
#define NEXT (GNODES * DSTALK)   // 150000

#define SCAN_BS 512
#define SCAN_NB ((NEXT + SCAN_BS - 1) / SCAN_BS)   // 293

// ---------------- scratch (static device globals; no allocs) ----------------
__device__ float g_HH[NEXT * HCH];    // h (== h0 between layers), [G,192] view
__device__ float g_T[NEXT * HCH];     // post left+right transform
__device__ int    g_cnt[NEXT];        // per-row degree counters
__device__ int    g_rowptr[NEXT + 1]; // CSR row pointers
__device__ int    g_tmp[NEXT];        // scatter cursors
__device__ int    g_bsum[SCAN_NB];    // scan block sums
__device__ float2 g_epack[NNZ_E];     // packed (col_bits, val) per edge

// ---------------- lin1: g_HH = elu(x @ W1^T + b1) ---------------------------
// M=50000, N=192, K=256. BM=128, BN=64, BK=16, 256 threads, 8x4 microtile.
__global__ __launch_bounds__(256) void lin1_kernel(const float* __restrict__ x,
                                                   const float* __restrict__ w,
                                                   const float* __restrict__ b) {
    __shared__ float As[16][132];
    __shared__ float Bs[16][68];
    const int bm = blockIdx.x * 128;
    const int bn = blockIdx.y * 64;
    const int tid = threadIdx.x;
    const int tx = tid & 15;
    const int ty = tid >> 4;

    float acc[8][4];
#pragma unroll
    for (int i = 0; i < 8; i++)
#pragma unroll
        for (int j = 0; j < 4; j++) acc[i][j] = 0.f;

    const int lrA = tid >> 1;
    const int lkA = (tid & 1) * 8;
    const int lrB = tid >> 2;
    const int lkB = (tid & 3) * 4;

    for (int k0 = 0; k0 < IN_DIM; k0 += 16) {
        float4 a0 = make_float4(0.f, 0.f, 0.f, 0.f);
        float4 a1 = make_float4(0.f, 0.f, 0.f, 0.f);
        int gr = bm + lrA;
        if (gr < GNODES) {
            a0 = *(const float4*)&x[gr * IN_DIM + k0 + lkA];
            a1 = *(const float4*)&x[gr * IN_DIM + k0 + lkA + 4];
        }
        As[lkA + 0][lrA] = a0.x; As[lkA + 1][lrA] = a0.y;
        As[lkA + 2][lrA] = a0.z; As[lkA + 3][lrA] = a0.w;
        As[lkA + 4][lrA] = a1.x; As[lkA + 5][lrA] = a1.y;
        As[lkA + 6][lrA] = a1.z; As[lkA + 7][lrA] = a1.w;

        float4 bv = *(const float4*)&w[(bn + lrB) * IN_DIM + k0 + lkB];
        Bs[lkB + 0][lrB] = bv.x; Bs[lkB + 1][lrB] = bv.y;
        Bs[lkB + 2][lrB] = bv.z; Bs[lkB + 3][lrB] = bv.w;
        __syncthreads();

#pragma unroll
        for (int k = 0; k < 16; k++) {
            float4 ar0 = *(float4*)&As[k][ty * 8];
            float4 ar1 = *(float4*)&As[k][ty * 8 + 4];
            float4 br  = *(float4*)&Bs[k][tx * 4];
            float ar[8] = {ar0.x, ar0.y, ar0.z, ar0.w, ar1.x, ar1.y, ar1.z, ar1.w};
            float brr[4] = {br.x, br.y, br.z, br.w};
#pragma unroll
            for (int i = 0; i < 8; i++)
#pragma unroll
                for (int j = 0; j < 4; j++) acc[i][j] += ar[i] * brr[j];
        }
        __syncthreads();
    }

    float4 bias = *(const float4*)&b[bn + tx * 4];
    float bb[4] = {bias.x, bias.y, bias.z, bias.w};
#pragma unroll
    for (int i = 0; i < 8; i++) {
        int gr = bm + ty * 8 + i;
        if (gr >= GNODES) continue;
        float4 r;
        float v;
        v = acc[i][0] + bb[0]; r.x = (v > 0.f) ? v : (expf(v) - 1.f);
        v = acc[i][1] + bb[1]; r.y = (v > 0.f) ? v : (expf(v) - 1.f);
        v = acc[i][2] + bb[2]; r.z = (v > 0.f) ? v : (expf(v) - 1.f);
        v = acc[i][3] + bb[3]; r.w = (v > 0.f) ? v : (expf(v) - 1.f);
        *(float4*)&g_HH[gr * 192 + bn + tx * 4] = r;
    }
}

// ------- fused left(3x3 stalk) + right(64x64 channel) transform -------------
__global__ __launch_bounds__(256) void transform_kernel(const float* __restrict__ leftw,
                                                        const float* __restrict__ rightw) {
    __shared__ float sh_h[48 * 68];
    __shared__ float sh_t[48 * 68];
    __shared__ float sh_R[64 * 68];
    const int tid = threadIdx.x;
    const int rowbase = blockIdx.x * 48;   // 3125 blocks * 48 = 150000 exact

    for (int i = tid; i < 1024; i += 256) {
        int row = i >> 4, c4 = i & 15;
        float4 v = ((const float4*)rightw)[i];
        *(float4*)&sh_R[row * 68 + c4 * 4] = v;
    }
    for (int i = tid; i < 768; i += 256) {
        int row = i >> 4, c4 = i & 15;
        float4 v = ((const float4*)g_HH)[(rowbase + row) * 16 + c4];
        *(float4*)&sh_h[row * 68 + c4 * 4] = v;
    }

    float Lw[9];
#pragma unroll
    for (int i = 0; i < 9; i++) Lw[i] = leftw[i];
    __syncthreads();

    for (int i = tid; i < 768; i += 256) {
        int row = i >> 4, c4 = i & 15;
        int e = row % 3;
        int gl = row - e;
        float4 h0 = *(float4*)&sh_h[(gl + 0) * 68 + c4 * 4];
        float4 h1 = *(float4*)&sh_h[(gl + 1) * 68 + c4 * 4];
        float4 h2 = *(float4*)&sh_h[(gl + 2) * 68 + c4 * 4];
        float w0 = Lw[e * 3 + 0], w1 = Lw[e * 3 + 1], w2 = Lw[e * 3 + 2];
        float4 t;
        t.x = w0 * h0.x + w1 * h1.x + w2 * h2.x;
        t.y = w0 * h0.y + w1 * h1.y + w2 * h2.y;
        t.z = w0 * h0.z + w1 * h1.z + w2 * h2.z;
        t.w = w0 * h0.w + w1 * h1.w + w2 * h2.w;
        *(float4*)&sh_t[row * 68 + c4 * 4] = t;
    }
    __syncthreads();

    const int cp = tid & 63;
    const int rg = tid >> 6;
    float acc[12];
#pragma unroll
    for (int i = 0; i < 12; i++) acc[i] = 0.f;
#pragma unroll
    for (int c0 = 0; c0 < 64; c0 += 4) {
        float4 rv = *(float4*)&sh_R[cp * 68 + c0];
#pragma unroll
        for (int i = 0; i < 12; i++) {
            float4 tv = *(float4*)&sh_t[(rg + 4 * i) * 68 + c0];
            acc[i] += tv.x * rv.x + tv.y * rv.y + tv.z * rv.z + tv.w * rv.w;
        }
    }
#pragma unroll
    for (int i = 0; i < 12; i++)
        g_T[(rowbase + rg + 4 * i) * 64 + cp] = acc[i];
}

// ---------------- CSR build: zero / hist / scan / scatter -------------------
__global__ __launch_bounds__(256) void zero_cnt_kernel() {
    int i = blockIdx.x * blockDim.x + threadIdx.x;
    if (i < NEXT) g_cnt[i] = 0;
}

__global__ __launch_bounds__(256) void hist_kernel(const int* __restrict__ rows) {
    int i = blockIdx.x * blockDim.x + threadIdx.x;
    if (i >= NNZ_E / 4) return;
    int4 r = ((const int4*)rows)[i];
    atomicAdd(&g_cnt[r.x], 1);
    atomicAdd(&g_cnt[r.y], 1);
    atomicAdd(&g_cnt[r.z], 1);
    atomicAdd(&g_cnt[r.w], 1);
}

__global__ __launch_bounds__(SCAN_BS) void scan1_kernel() {
    __shared__ int s[SCAN_BS];
    int t = threadIdx.x;
    int i = blockIdx.x * SCAN_BS + t;
    int v = (i < NEXT) ? g_cnt[i] : 0;
    s[t] = v;
    __syncthreads();
#pragma unroll
    for (int off = 1; off < SCAN_BS; off <<= 1) {
        int x = (t >= off) ? s[t - off] : 0;
        __syncthreads();
        s[t] += x;
        __syncthreads();
    }
    if (i < NEXT) g_rowptr[i] = s[t] - v;   // block-local exclusive
    if (t == SCAN_BS - 1) g_bsum[blockIdx.x] = s[t];
}

__global__ __launch_bounds__(SCAN_BS) void scan2_kernel() {
    __shared__ int s[SCAN_BS];
    int t = threadIdx.x;
    int v = (t < SCAN_NB) ? g_bsum[t] : 0;
    s[t] = v;
    __syncthreads();
#pragma unroll
    for (int off = 1; off < SCAN_BS; off <<= 1) {
        int x = (t >= off) ? s[t - off] : 0;
        __syncthreads();
        s[t] += x;
        __syncthreads();
    }
    if (t < SCAN_NB) g_bsum[t] = s[t] - v;  // exclusive
}

__global__ __launch_bounds__(256) void scan3_kernel() {
    int i = blockIdx.x * blockDim.x + threadIdx.x;
    if (i < NEXT) {
        int rp = g_rowptr[i] + g_bsum[i / SCAN_BS];
        g_rowptr[i] = rp;
        g_tmp[i] = rp;
    }
    if (i == 0) g_rowptr[NEXT] = NNZ_E;
}

__global__ __launch_bounds__(256) void scatter_kernel(const int* __restrict__ rows,
                                                      const int* __restrict__ cols,
                                                      const float* __restrict__ vals) {
    int i = blockIdx.x * blockDim.x + threadIdx.x;
    if (i >= NNZ_E / 4) return;
    int4 r = ((const int4*)rows)[i];
    int4 c = ((const int4*)cols)[i];
    float4 v = ((const float4*)vals)[i];
    int p;
    p = atomicAdd(&g_tmp[r.x], 1); g_epack[p] = make_float2(__int_as_float(c.x), v.x);
    p = atomicAdd(&g_tmp[r.y], 1); g_epack[p] = make_float2(__int_as_float(c.y), v.y);
    p = atomicAdd(&g_tmp[r.z], 1); g_epack[p] = make_float2(__int_as_float(c.z), v.z);
    p = atomicAdd(&g_tmp[r.w], 1); g_epack[p] = make_float2(__int_as_float(c.w), v.w);
}

// ------- pull-mode SpMM + fused epilogue: half-warp per row -----------------
// h = elu(sum_e val_e * T[col_e]);  HH[row] = gate*HH[row] - h
__global__ __launch_bounds__(256) void spmm_fused_kernel(const float* __restrict__ eps, int l) {
    int gid = blockIdx.x * 256 + threadIdx.x;
    int row = gid >> 4;
    int hl = gid & 15;
    if (row >= NEXT) return;

    int s = __ldg(&g_rowptr[row]);
    int e = __ldg(&g_rowptr[row + 1]);
    const float4* __restrict__ T4 = (const float4*)g_T;

    float4 acc = make_float4(0.f, 0.f, 0.f, 0.f);
    int k = s;
    for (; k + 1 < e; k += 2) {
        float2 p0 = __ldg(&g_epack[k]);
        float2 p1 = __ldg(&g_epack[k + 1]);
        float4 t0 = __ldg(&T4[__float_as_int(p0.x) * 16 + hl]);
        float4 t1 = __ldg(&T4[__float_as_int(p1.x) * 16 + hl]);
        acc.x += p0.y * t0.x + p1.y * t1.x;
        acc.y += p0.y * t0.y + p1.y * t1.y;
        acc.z += p0.y * t0.z + p1.y * t1.z;
        acc.w += p0.y * t0.w + p1.y * t1.w;
    }
    if (k < e) {
        float2 p0 = __ldg(&g_epack[k]);
        float4 t0 = __ldg(&T4[__float_as_int(p0.x) * 16 + hl]);
        acc.x += p0.y * t0.x;
        acc.y += p0.y * t0.y;
        acc.z += p0.y * t0.z;
        acc.w += p0.y * t0.w;
    }

    int d = row % 3;
    float gate = 1.f + tanhf(__ldg(&eps[l * 3 + d]));
    float4 h = ((const float4*)g_HH)[row * 16 + hl];
    float ex, ey, ez, ew;
    ex = (acc.x > 0.f) ? acc.x : (expf(acc.x) - 1.f);
    ey = (acc.y > 0.f) ? acc.y : (expf(acc.y) - 1.f);
    ez = (acc.z > 0.f) ? acc.z : (expf(acc.z) - 1.f);
    ew = (acc.w > 0.f) ? acc.w : (expf(acc.w) - 1.f);
    float4 r;
    r.x = gate * h.x - ex;
    r.y = gate * h.y - ey;
    r.z = gate * h.z - ez;
    r.w = gate * h.w - ew;
    ((float4*)g_HH)[row * 16 + hl] = r;
}

// ---------------- lin2 + log_softmax ----------------------------------------
__global__ __launch_bounds__(256) void out_kernel(const float* __restrict__ w2,
                                                  const float* __restrict__ b2,
                                                  float* __restrict__ out) {
    __shared__ float sW[40 * 193];
    __shared__ float sH[16 * 192];
    const int tid = threadIdx.x;
    const int gbase = blockIdx.x * 16;

    for (int i = tid; i < 40 * 192; i += 256)
        sW[(i / 192) * 193 + (i % 192)] = w2[i];
    for (int i = tid; i < 16 * 192; i += 256)
        sH[i] = g_HH[gbase * 192 + i];
    __syncthreads();

    const int warp = tid >> 5, lane = tid & 31;
#pragma unroll
    for (int rr = 0; rr < 2; rr++) {
        int row = warp * 2 + rr;
        int g = gbase + row;
        float acc1 = 0.f, acc2 = 0.f;
        const float* hrow = &sH[row * 192];
#pragma unroll 8
        for (int j = 0; j < 192; j++) {
            float hv = hrow[j];
            acc1 += hv * sW[lane * 193 + j];
            if (lane < 8) acc2 += hv * sW[(lane + 32) * 193 + j];
        }
        acc1 += b2[lane];
        float v2 = (lane < 8) ? (acc2 + b2[lane + 32]) : -INFINITY;

        float m = fmaxf(acc1, v2);
#pragma unroll
        for (int off = 16; off; off >>= 1) m = fmaxf(m, __shfl_xor_sync(0xffffffffu, m, off));
        float s = expf(acc1 - m) + ((lane < 8) ? expf(v2 - m) : 0.f);
#pragma unroll
        for (int off = 16; off; off >>= 1) s += __shfl_xor_sync(0xffffffffu, s, off);
        float ls = m + logf(s);

        out[g * OUT_DIM + lane] = acc1 - ls;
        if (lane < 8) out[g * OUT_DIM + 32 + lane] = v2 - ls;
    }
}

// ---------------- launch -----------------------------------------------------
extern "C" void kernel_launch(void* const* d_in, const int* in_sizes, int n_in,
                              void* d_out, int out_size) {
    const float* x   = (const float*)d_in[0];
    const int*   lr  = (const int*)d_in[1];
    const int*   lc  = (const int*)d_in[2];
    const float* lv  = (const float*)d_in[3];
    const float* w1  = (const float*)d_in[4];
    const float* b1  = (const float*)d_in[5];
    const float* lw  = (const float*)d_in[6];   // [L,3,3]
    const float* rw  = (const float*)d_in[7];   // [L,64,64]
    const float* eps = (const float*)d_in[8];   // [L,3,1]
    const float* w2  = (const float*)d_in[9];
    const float* b2  = (const float*)d_in[10];
    float* out = (float*)d_out;

    // lin1 (independent of CSR build)
    lin1_kernel<<<dim3((GNODES + 127) / 128, 3), 256>>>(x, w1, b1);

    // CSR build (once per launch; reused by all 4 layers)
    zero_cnt_kernel<<<(NEXT + 255) / 256, 256>>>();
    hist_kernel<<<(NNZ_E / 4 + 255) / 256, 256>>>(lr);
    scan1_kernel<<<SCAN_NB, SCAN_BS>>>();
    scan2_kernel<<<1, SCAN_BS>>>();
    scan3_kernel<<<(NEXT + 255) / 256, 256>>>();
    scatter_kernel<<<(NNZ_E / 4 + 255) / 256, 256>>>(lr, lc, lv);

    for (int l = 0; l < NLAYERS; l++) {
        transform_kernel<<<NEXT / 48, 256>>>(lw + l * 9, rw + l * 64 * 64);
        spmm_fused_kernel<<<(NEXT * 16 + 255) / 256, 256>>>(eps, l);
    }
    out_kernel<<<GNODES / 16, 256>>>(w2, b2, out);
}